// round 2
// baseline (speedup 1.0000x reference)
#include <cuda_runtime.h>

#define H  128
#define NH 8

// Scratch (no allocations allowed): transposed Wk/Wrk (12 x 128x128) + ping-pong x_m buffers.
__device__ float g_WT[12 * H * H];
__device__ float g_buf0[2304 * H];
__device__ float g_buf1[2304 * H];

// Transpose Wk / Wrk for each stage & layer. slot = pair*2 + layer.
// pair: 0=Wk_m2t 1=Wrk_m2t 2=Wk_m2pl 3=Wrk_m2pl 4=Wk_m2a 5=Wrk_m2a
__global__ void transpose_k(const float* p0, const float* p1, const float* p2,
                            const float* p3, const float* p4, const float* p5)
{
    const float* ps[6] = {p0, p1, p2, p3, p4, p5};
    int slot = blockIdx.x;                       // 0..11
    const float* Wm = ps[slot >> 1] + (slot & 1) * H * H;
    float* O = g_WT + slot * H * H;
    int t = threadIdx.x;                         // 0..127
    for (int c = 0; c < H; ++c)
        O[c * H + t] = Wm[t * H + c];
}

// One block = one query. 128 threads.
// stage: 1 = m2t (S=50, no gather), 2 = m2pl (S=32, knn over M=128),
//        3 = m2a (S=16, knn over N=48, keys from x_a[.., 49, :])
__global__ __launch_bounds__(128) void attn_stage(
    const float* __restrict__ xin, float* __restrict__ xout,
    const float* __restrict__ ksrc, const float* __restrict__ rpesrc,
    const int* __restrict__ knn, const unsigned char* __restrict__ mask,
    const float* __restrict__ Wq,  const float* __restrict__ WkT,
    const float* __restrict__ Wv,  const float* __restrict__ WrkT,
    const float* __restrict__ Wrv, const float* __restrict__ Wo,
    int stage, int S)
{
    extern __shared__ float sm[];
    float* sm_q  = sm;              // 128
    float* sm_qh = sm + 128;        // 128 (reused later as out_full)
    float* sm_u  = sm + 256;        // 1024  u[i*8+n]
    float* sm_w  = sm + 1280;       // 1024  w[i*8+n]
    float* sm_sc = sm + 2304;       // 512   scores [s*8+n]
    float* sm_vb = sm + 2816;       // 8*136
    float* sm_rb = sm + 3904;       // 8*136
    float* sm_k  = sm + 4992;       // S*132
    float* sm_r  = sm_k + S * 132;  // S*132

    __shared__ long long kbase[64];
    __shared__ long long rbase[64];
    __shared__ int       mflag[64];

    const int q = blockIdx.x;
    const int t = threadIdx.x;

    sm_q[t] = xin[q * H + t];

    if (t < S) {
        long long kb, rb; int mf;
        if (stage == 1) {
            kb = ((long long)q * S + t) * H; rb = kb;
            mf = mask[q * S + t];
        } else if (stage == 2) {
            int idx = knn[q * 32 + t];
            kb = ((long long)q * 128 + idx) * H; rb = kb;
            mf = mask[q * 128 + idx];
        } else {
            int g = q / 48, qn = q % 48;
            int idx = knn[(g * 48 + qn) * 16 + t];
            kb = (((long long)(g * 48 + idx)) * 50 + 49) * H;   // x_a[:, HT-1, :]
            rb = (((long long)(g * 48 + qn)) * 48 + idx) * H;
            mf = mask[(g * 48 + qn) * 48 + idx];
        }
        kbase[t] = kb; rbase[t] = rb; mflag[t] = mf;
    }
    __syncthreads();

    // qh = q @ Wq   (coalesced over t)
    float acc = 0.f;
    #pragma unroll 8
    for (int i = 0; i < H; ++i) acc += sm_q[i] * Wq[i * H + t];
    sm_qh[t] = acc;
    __syncthreads();

    // u[n][i] = sum_d qh[n*16+d] * Wk[i, n*16+d] via WkT, coalesced over i=t
    {
        float uu[NH], ww[NH];
        #pragma unroll
        for (int n = 0; n < NH; ++n) { uu[n] = 0.f; ww[n] = 0.f; }
        #pragma unroll
        for (int n = 0; n < NH; ++n) {
            #pragma unroll
            for (int d = 0; d < 16; ++d) {
                float qv = sm_qh[n * 16 + d];
                uu[n] += qv * WkT[(n * 16 + d) * H + t];
                ww[n] += qv * WrkT[(n * 16 + d) * H + t];
            }
        }
        #pragma unroll
        for (int n = 0; n < NH; ++n) { sm_u[t * NH + n] = uu[n]; sm_w[t * NH + n] = ww[n]; }
    }

    // Stage keys + rpe rows in smem (rows padded to 132 floats)
    for (int e = t; e < S * H; e += 128) {
        int s = e >> 7, i = e & 127;
        sm_k[s * 132 + i] = ksrc[kbase[s] + i];
        sm_r[s * 132 + i] = rpesrc[rbase[s] + i];
    }
    __syncthreads();

    // scores[s][n] = (u_n . k_s + w_n . rpe_s) / sqrt(16)
    for (int e = t; e < NH * S; e += 128) {
        int s = e >> 3, n = e & 7;
        const float* kk = &sm_k[s * 132];
        const float* rr = &sm_r[s * 132];
        float sc = 0.f;
        #pragma unroll 8
        for (int i = 0; i < H; ++i)
            sc += sm_u[i * NH + n] * kk[i] + sm_w[i * NH + n] * rr[i];
        sc *= 0.25f;
        if (mflag[s]) sc = -1e9f;
        sm_sc[s * NH + n] = sc;
    }
    __syncthreads();

    // softmax per head (S <= 50: serial per head is cheap)
    if (t < NH) {
        float mx = -1e30f;
        for (int s = 0; s < S; ++s) mx = fmaxf(mx, sm_sc[s * NH + t]);
        float sum = 0.f;
        for (int s = 0; s < S; ++s) {
            float p = __expf(sm_sc[s * NH + t] - mx);
            sm_sc[s * NH + t] = p; sum += p;
        }
        float inv = 1.f / sum;
        for (int s = 0; s < S; ++s) sm_sc[s * NH + t] *= inv;
    }
    __syncthreads();

    // vbar[n][i] = sum_s p[n,s] k[s,i];  rbar likewise with rpe (v rows == k rows)
    {
        float vb[NH], rb2[NH];
        #pragma unroll
        for (int n = 0; n < NH; ++n) { vb[n] = 0.f; rb2[n] = 0.f; }
        for (int s = 0; s < S; ++s) {
            float kv = sm_k[s * 132 + t];
            float rv = sm_r[s * 132 + t];
            #pragma unroll
            for (int n = 0; n < NH; ++n) {
                float p = sm_sc[s * NH + n];
                vb[n]  += p * kv;
                rb2[n] += p * rv;
            }
        }
        #pragma unroll
        for (int n = 0; n < NH; ++n) { sm_vb[n * 136 + t] = vb[n]; sm_rb[n * 136 + t] = rb2[n]; }
    }
    __syncthreads();

    // out_full[c] = vbar[n_c] @ Wv[:,c] + rbar[n_c] @ Wrv[:,c],  n_c = c/16
    {
        int n = t >> 4;
        float o = 0.f;
        #pragma unroll 8
        for (int i = 0; i < H; ++i)
            o += sm_vb[n * 136 + i] * Wv[i * H + t] + sm_rb[n * 136 + i] * Wrv[i * H + t];
        __syncthreads();
        sm_qh[t] = o;           // reuse as out_full
    }
    __syncthreads();

    // x_new = q + out_full @ Wo
    float x = sm_q[t];
    #pragma unroll 8
    for (int c = 0; c < H; ++c) x += sm_qh[c] * Wo[c * H + t];
    xout[q * H + t] = x;
}

extern "C" void kernel_launch(void* const* d_in, const int* in_sizes, int n_in,
                              void* d_out, int out_size)
{
    // Detect input ordering: signature order has Wq_m2t (32768 elems) at slot 6;
    // dict order has knn_idxs_m2pl (73728) there.
    bool sig = (in_sizes[6] == 32768);

    const float* x_m    = (const float*)d_in[0];
    const float* x_a    = (const float*)d_in[1];
    const float* x_pl   = (const float*)d_in[2];
    const float* rpe_t  = (const float*)d_in[3];
    const float* rpe_pl = (const float*)d_in[4];
    const float* rpe_a  = (const float*)d_in[5];

    const float* W[3][6];   // [stage][Wq,Wk,Wv,Wrk,Wrv,Wo], each [2,128,128]
    int wb = sig ? 6 : 11;
    for (int s = 0; s < 3; ++s)
        for (int j = 0; j < 6; ++j)
            W[s][j] = (const float*)d_in[wb + s * 6 + j];

    int kb = sig ? 24 : 6;
    const int* knn_pl = (const int*)d_in[kb + 0];
    const int* knn_a  = (const int*)d_in[kb + 1];
    const unsigned char* mk_t  = (const unsigned char*)d_in[kb + 2];
    const unsigned char* mk_pl = (const unsigned char*)d_in[kb + 3];
    const unsigned char* mk_a  = (const unsigned char*)d_in[kb + 4];

    // Allow >48KB dynamic smem (idempotent, immediate host-side call).
    cudaFuncSetAttribute(attn_stage, cudaFuncAttributeMaxDynamicSharedMemorySize, 80 * 1024);

    float *buf0, *buf1, *wt;
    cudaGetSymbolAddress((void**)&buf0, g_buf0);
    cudaGetSymbolAddress((void**)&buf1, g_buf1);
    cudaGetSymbolAddress((void**)&wt,   g_WT);

    // Pre-transpose Wk / Wrk for all 3 stages x 2 layers.
    transpose_k<<<12, 128>>>(W[0][1], W[0][3], W[1][1], W[1][3], W[2][1], W[2][3]);

    const int  Ss[3]    = {50, 32, 16};
    const float* cur = x_m;
    float* bufs[2] = {buf0, buf1};
    int bi = 0;

    for (int l = 0; l < 2; ++l) {
        for (int s = 0; s < 3; ++s) {
            float* outp = (l == 1 && s == 2) ? (float*)d_out : bufs[bi];
            int S = Ss[s];
            const float* ksrc = (s == 0) ? x_a : (s == 1) ? x_pl : x_a;
            const float* rp   = (s == 0) ? rpe_t : (s == 1) ? rpe_pl : rpe_a;
            const int*   kn   = (s == 1) ? knn_pl : (s == 2) ? knn_a : (const int*)0;
            const unsigned char* mk = (s == 0) ? mk_t : (s == 1) ? mk_pl : mk_a;

            const float* Wq   = W[s][0] + l * H * H;
            const float* Wv   = W[s][2] + l * H * H;
            const float* Wrv  = W[s][4] + l * H * H;
            const float* Wo   = W[s][5] + l * H * H;
            const float* WkT  = wt + ((s * 2 + 0) * 2 + l) * H * H;
            const float* WrkT = wt + ((s * 2 + 1) * 2 + l) * H * H;

            size_t smem = (size_t)(4992 + S * 132 * 2) * sizeof(float);
            attn_stage<<<2304, 128, smem>>>(cur, outp, ksrc, rp, kn, mk,
                                            Wq, WkT, Wv, WrkT, Wrv, Wo,
                                            s + 1, S);
            cur = outp;
            bi ^= 1;
        }
    }
}

// round 3
// speedup vs baseline: 2.1781x; 2.1781x over previous
#include <cuda_runtime.h>
#include <cstdint>

#define H  128
#define NH 8

// Scratch: transposed Wk/Wrk (12 x 128x128) + ping-pong x_m buffers.
__device__ float g_WT[12 * H * H];
__device__ float g_buf0[2304 * H];
__device__ float g_buf1[2304 * H];

__global__ void transpose_k(const float* p0, const float* p1, const float* p2,
                            const float* p3, const float* p4, const float* p5)
{
    const float* ps[6] = {p0, p1, p2, p3, p4, p5};
    int slot = blockIdx.x;                       // 0..11
    const float* Wm = ps[slot >> 1] + (slot & 1) * H * H;
    float* O = g_WT + slot * H * H;
    int t = threadIdx.x;                         // 0..127
    for (int c = 0; c < H; ++c)
        O[c * H + t] = Wm[t * H + c];
}

__device__ __forceinline__ void cp16(uint32_t dst, const float* src) {
    asm volatile("cp.async.cg.shared.global [%0], [%1], 16;" :: "r"(dst), "l"(src));
}

// One block = one query. 128 threads.
__global__ __launch_bounds__(128) void attn_stage(
    const float* __restrict__ xin, float* __restrict__ xout,
    const float* __restrict__ ksrc, const float* __restrict__ rpesrc,
    const int* __restrict__ knn, const unsigned char* __restrict__ mask,
    const float* __restrict__ Wq,  const float* __restrict__ WkT,
    const float* __restrict__ Wv,  const float* __restrict__ WrkT,
    const float* __restrict__ Wrv, const float* __restrict__ Wo,
    int stage, int S)
{
    extern __shared__ float sm[];
    float* sm_q  = sm;              // 128
    float* sm_qh = sm + 128;        // 128 (later reused as out_full)
    float* sm_u  = sm + 256;        // 1024  u[i*8+n]
    float* sm_w  = sm + 1280;       // 1024  w[i*8+n]
    float* sm_sc = sm + 2304;       // 512   scores [s*8+n]
    float* sm_vb = sm + 2816;       // 8*136
    float* sm_rb = sm + 3904;       // 8*136
    float* sm_k  = sm + 4992;       // S*132
    float* sm_r  = sm_k + S * 132;  // S*132

    __shared__ long long kbase[64];
    __shared__ long long rbase[64];
    __shared__ int       mflag[64];

    const int q = blockIdx.x;
    const int t = threadIdx.x;

    sm_q[t] = xin[q * H + t];

    if (t < S) {
        long long kb, rb; int mf;
        if (stage == 1) {
            kb = ((long long)q * S + t) * H; rb = kb;
            mf = mask[q * S + t];
        } else if (stage == 2) {
            int idx = knn[q * 32 + t];
            kb = ((long long)q * 128 + idx) * H; rb = kb;
            mf = mask[q * 128 + idx];
        } else {
            int g = q / 48, qn = q % 48;
            int idx = knn[(g * 48 + qn) * 16 + t];
            kb = (((long long)(g * 48 + idx)) * 50 + 49) * H;   // x_a[:, HT-1, :]
            rb = (((long long)(g * 48 + qn)) * 48 + idx) * H;
            mf = mask[(g * 48 + qn) * 48 + idx];
        }
        kbase[t] = kb; rbase[t] = rb; mflag[t] = mf;
    }
    __syncthreads();

    // Kick off async staging of k / rpe rows (overlaps with qh + u/w compute below).
    {
        uint32_t smk = (uint32_t)__cvta_generic_to_shared(sm_k);
        uint32_t smr = (uint32_t)__cvta_generic_to_shared(sm_r);
        int chunks = S * 32;   // 16B chunks per tensor
        for (int c = t; c < chunks; c += 128) {
            int s = c >> 5, j = c & 31;
            cp16(smk + s * 528 + j * 16, ksrc   + kbase[s] + j * 4);
            cp16(smr + s * 528 + j * 16, rpesrc + rbase[s] + j * 4);
        }
        asm volatile("cp.async.commit_group;");
    }

    // qh = q @ Wq   (4 independent accumulators)
    {
        float a0 = 0.f, a1 = 0.f, a2 = 0.f, a3 = 0.f;
        #pragma unroll
        for (int i = 0; i < H; i += 4) {
            a0 += sm_q[i    ] * Wq[(i    ) * H + t];
            a1 += sm_q[i + 1] * Wq[(i + 1) * H + t];
            a2 += sm_q[i + 2] * Wq[(i + 2) * H + t];
            a3 += sm_q[i + 3] * Wq[(i + 3) * H + t];
        }
        sm_qh[t] = (a0 + a1) + (a2 + a3);
    }
    __syncthreads();

    // u[n][i] = qh_n . WkT rows  (16 independent accumulator chains)
    {
        float uu[NH], ww[NH];
        #pragma unroll
        for (int n = 0; n < NH; ++n) { uu[n] = 0.f; ww[n] = 0.f; }
        #pragma unroll
        for (int n = 0; n < NH; ++n) {
            #pragma unroll
            for (int d = 0; d < 16; ++d) {
                float qv = sm_qh[n * 16 + d];
                uu[n] += qv * WkT [(n * 16 + d) * H + t];
                ww[n] += qv * WrkT[(n * 16 + d) * H + t];
            }
        }
        #pragma unroll
        for (int n = 0; n < NH; ++n) { sm_u[t * NH + n] = uu[n]; sm_w[t * NH + n] = ww[n]; }
    }

    asm volatile("cp.async.wait_group 0;");
    __syncthreads();

    // scores[s][n] = (u_n . k_s + w_n . rpe_s) / 4   (4 accumulators)
    for (int e = t; e < NH * S; e += 128) {
        int s = e >> 3, n = e & 7;
        const float* kk = &sm_k[s * 132];
        const float* rr = &sm_r[s * 132];
        float s0 = 0.f, s1 = 0.f, s2 = 0.f, s3 = 0.f;
        #pragma unroll
        for (int i = 0; i < H; i += 2) {
            s0 += sm_u[(i    ) * NH + n] * kk[i    ];
            s1 += sm_w[(i    ) * NH + n] * rr[i    ];
            s2 += sm_u[(i + 1) * NH + n] * kk[i + 1];
            s3 += sm_w[(i + 1) * NH + n] * rr[i + 1];
        }
        float sc = ((s0 + s1) + (s2 + s3)) * 0.25f;
        if (mflag[s]) sc = -1e9f;
        sm_sc[e] = sc;
    }
    __syncthreads();

    // softmax per head: 8 lanes per head, shuffle reduction (lanes of a head
    // are contiguous within a warp, so xor-shuffles 1/2/4 stay in-group).
    if (t < 64) {
        int n = t >> 3, j = t & 7;
        float mx = -1e30f;
        for (int s = j; s < S; s += 8) mx = fmaxf(mx, sm_sc[s * NH + n]);
        #pragma unroll
        for (int o = 4; o; o >>= 1) mx = fmaxf(mx, __shfl_xor_sync(0xffffffffu, mx, o));
        float sum = 0.f;
        for (int s = j; s < S; s += 8) {
            float p = __expf(sm_sc[s * NH + n] - mx);
            sm_sc[s * NH + n] = p; sum += p;
        }
        #pragma unroll
        for (int o = 4; o; o >>= 1) sum += __shfl_xor_sync(0xffffffffu, sum, o);
        float inv = 1.f / sum;
        for (int s = j; s < S; s += 8) sm_sc[s * NH + n] *= inv;
    }
    __syncthreads();

    // vbar[n][i] = sum_s p[n,s] k[s,i];  rbar likewise (16 independent chains)
    {
        float vb[NH], rb2[NH];
        #pragma unroll
        for (int n = 0; n < NH; ++n) { vb[n] = 0.f; rb2[n] = 0.f; }
        for (int s = 0; s < S; ++s) {
            float kv = sm_k[s * 132 + t];
            float rv = sm_r[s * 132 + t];
            #pragma unroll
            for (int n = 0; n < NH; ++n) {
                float p = sm_sc[s * NH + n];
                vb[n]  += p * kv;
                rb2[n] += p * rv;
            }
        }
        #pragma unroll
        for (int n = 0; n < NH; ++n) { sm_vb[n * 136 + t] = vb[n]; sm_rb[n * 136 + t] = rb2[n]; }
    }
    __syncthreads();

    // out_full[c] = vbar[n_c] @ Wv[:,c] + rbar[n_c] @ Wrv[:,c]
    {
        int n = t >> 4;
        float o0 = 0.f, o1 = 0.f, o2 = 0.f, o3 = 0.f;
        #pragma unroll
        for (int i = 0; i < H; i += 2) {
            o0 += sm_vb[n * 136 + i    ] * Wv [(i    ) * H + t];
            o1 += sm_rb[n * 136 + i    ] * Wrv[(i    ) * H + t];
            o2 += sm_vb[n * 136 + i + 1] * Wv [(i + 1) * H + t];
            o3 += sm_rb[n * 136 + i + 1] * Wrv[(i + 1) * H + t];
        }
        float o = (o0 + o1) + (o2 + o3);
        __syncthreads();
        sm_qh[t] = o;           // reuse as out_full
    }
    __syncthreads();

    // x_new = q + out_full @ Wo   (4 accumulators)
    {
        float x0 = sm_q[t], x1 = 0.f, x2 = 0.f, x3 = 0.f;
        #pragma unroll
        for (int c = 0; c < H; c += 4) {
            x0 += sm_qh[c    ] * Wo[(c    ) * H + t];
            x1 += sm_qh[c + 1] * Wo[(c + 1) * H + t];
            x2 += sm_qh[c + 2] * Wo[(c + 2) * H + t];
            x3 += sm_qh[c + 3] * Wo[(c + 3) * H + t];
        }
        xout[q * H + t] = (x0 + x1) + (x2 + x3);
    }
}

extern "C" void kernel_launch(void* const* d_in, const int* in_sizes, int n_in,
                              void* d_out, int out_size)
{
    bool sig = (in_sizes[6] == 32768);

    const float* x_m    = (const float*)d_in[0];
    const float* x_a    = (const float*)d_in[1];
    const float* x_pl   = (const float*)d_in[2];
    const float* rpe_t  = (const float*)d_in[3];
    const float* rpe_pl = (const float*)d_in[4];
    const float* rpe_a  = (const float*)d_in[5];

    const float* W[3][6];
    int wb = sig ? 6 : 11;
    for (int s = 0; s < 3; ++s)
        for (int j = 0; j < 6; ++j)
            W[s][j] = (const float*)d_in[wb + s * 6 + j];

    int kb = sig ? 24 : 6;
    const int* knn_pl = (const int*)d_in[kb + 0];
    const int* knn_a  = (const int*)d_in[kb + 1];
    const unsigned char* mk_t  = (const unsigned char*)d_in[kb + 2];
    const unsigned char* mk_pl = (const unsigned char*)d_in[kb + 3];
    const unsigned char* mk_a  = (const unsigned char*)d_in[kb + 4];

    cudaFuncSetAttribute(attn_stage, cudaFuncAttributeMaxDynamicSharedMemorySize, 80 * 1024);
    cudaFuncSetAttribute(attn_stage, cudaFuncAttributePreferredSharedMemoryCarveout, 100);

    float *buf0, *buf1, *wt;
    cudaGetSymbolAddress((void**)&buf0, g_buf0);
    cudaGetSymbolAddress((void**)&buf1, g_buf1);
    cudaGetSymbolAddress((void**)&wt,   g_WT);

    transpose_k<<<12, 128>>>(W[0][1], W[0][3], W[1][1], W[1][3], W[2][1], W[2][3]);

    const int Ss[3] = {50, 32, 16};
    const float* cur = x_m;
    float* bufs[2] = {buf0, buf1};
    int bi = 0;

    for (int l = 0; l < 2; ++l) {
        for (int s = 0; s < 3; ++s) {
            float* outp = (l == 1 && s == 2) ? (float*)d_out : bufs[bi];
            int S = Ss[s];
            const float* ksrc = (s == 1) ? x_pl : x_a;
            const float* rp   = (s == 0) ? rpe_t : (s == 1) ? rpe_pl : rpe_a;
            const int*   kn   = (s == 1) ? knn_pl : (s == 2) ? knn_a : (const int*)0;
            const unsigned char* mk = (s == 0) ? mk_t : (s == 1) ? mk_pl : mk_a;

            const float* Wq   = W[s][0] + l * H * H;
            const float* Wv   = W[s][2] + l * H * H;
            const float* Wrv  = W[s][4] + l * H * H;
            const float* Wo   = W[s][5] + l * H * H;
            const float* WkT  = wt + ((s * 2 + 0) * 2 + l) * H * H;
            const float* WrkT = wt + ((s * 2 + 1) * 2 + l) * H * H;

            size_t smem = (size_t)(4992 + S * 132 * 2) * sizeof(float);
            attn_stage<<<2304, 128, smem>>>(cur, outp, ksrc, rp, kn, mk,
                                            Wq, WkT, Wv, WrkT, Wrv, Wo,
                                            s + 1, S);
            cur = outp;
            bi ^= 1;
        }
    }
}